// round 4
// baseline (speedup 1.0000x reference)
#include <cuda_runtime.h>

// Inverse 2D Haar DWT, collapsed to the per-2x2-block butterfly:
//   out[2i  ,2j  ] = 0.5*(LL + LH + HL + HH)
//   out[2i  ,2j+1] = 0.5*(LL - LH + HL - HH)
//   out[2i+1,2j  ] = 0.5*(LL + LH - HL - HH)
//   out[2i+1,2j+1] = 0.5*(LL - LH - HL + HH)
//
// Shapes: in (32,128,56,56) f32 x4 -> out (32,128,112,112) f32
//
// Vertical pairing: each thread handles one input column-pair (float2) in
// TWO consecutive input rows (i0 = 2*ip, i0+1). Per-instruction warp access
// patterns are identical to the best R1/R3 kernel (float2 loads contiguous
// across the warp, float4 stores contiguous per output row); this version
// just doubles in-flight loads per thread (MLP 8) and tightens DRAM page
// locality (input rows 224B apart, output rows a contiguous 1792B span).

#define H_IN   56
#define W_IN   56
#define H_OUT  112
#define W_OUT  112
#define WPAIRS (W_IN / 2)   // 28
#define IPAIRS (H_IN / 2)   // 28

__device__ __forceinline__ void butterfly2(float2 ll, float2 lh, float2 hl, float2 hh,
                                           float4& row_even, float4& row_odd)
{
    float p0 = ll.x + hl.x, m0 = ll.x - hl.x;
    float q0 = lh.x + hh.x, r0 = lh.x - hh.x;
    float p1 = ll.y + hl.y, m1 = ll.y - hl.y;
    float q1 = lh.y + hh.y, r1 = lh.y - hh.y;
    row_even = make_float4(0.5f * (p0 + q0), 0.5f * (p0 - q0),
                           0.5f * (p1 + q1), 0.5f * (p1 - q1));
    row_odd  = make_float4(0.5f * (m0 + r0), 0.5f * (m0 - r0),
                           0.5f * (m1 + r1), 0.5f * (m1 - r1));
}

__global__ __launch_bounds__(256)
void idwt_haar_kernel(const float* __restrict__ LL,
                      const float* __restrict__ LH,
                      const float* __restrict__ HL,
                      const float* __restrict__ HH,
                      float* __restrict__ out,
                      int total)   // = N*C*IPAIRS*WPAIRS
{
    int idx = blockIdx.x * blockDim.x + threadIdx.x;
    if (idx >= total) return;

    int jj = idx % WPAIRS;                 // input col pair -> cols 2jj, 2jj+1
    int t  = idx / WPAIRS;
    int ip = t % IPAIRS;                   // input row pair -> rows 2ip, 2ip+1
    int ch = t / IPAIRS;                   // fused (batch*channel)

    int  i0      = 2 * ip;
    long in_off  = (long)ch * (H_IN * W_IN) + i0 * W_IN + 2 * jj;
    long out_off = (long)ch * (H_OUT * W_OUT) + (2 * i0) * W_OUT + 4 * jj;

    // front-batched loads: 8 independent LDG.64 in flight
    float2 ll0 = __ldcs(reinterpret_cast<const float2*>(LL + in_off));
    float2 lh0 = __ldcs(reinterpret_cast<const float2*>(LH + in_off));
    float2 hl0 = __ldcs(reinterpret_cast<const float2*>(HL + in_off));
    float2 hh0 = __ldcs(reinterpret_cast<const float2*>(HH + in_off));
    float2 ll1 = __ldcs(reinterpret_cast<const float2*>(LL + in_off + W_IN));
    float2 lh1 = __ldcs(reinterpret_cast<const float2*>(LH + in_off + W_IN));
    float2 hl1 = __ldcs(reinterpret_cast<const float2*>(HL + in_off + W_IN));
    float2 hh1 = __ldcs(reinterpret_cast<const float2*>(HH + in_off + W_IN));

    float4 e0, o0, e1, o1;
    butterfly2(ll0, lh0, hl0, hh0, e0, o0);
    butterfly2(ll1, lh1, hl1, hh1, e1, o1);

    __stcs(reinterpret_cast<float4*>(out + out_off),             e0);
    __stcs(reinterpret_cast<float4*>(out + out_off + W_OUT),     o0);
    __stcs(reinterpret_cast<float4*>(out + out_off + 2 * W_OUT), e1);
    __stcs(reinterpret_cast<float4*>(out + out_off + 3 * W_OUT), o1);
}

extern "C" void kernel_launch(void* const* d_in, const int* in_sizes, int n_in,
                              void* d_out, int out_size)
{
    const float* LL = (const float*)d_in[0];
    const float* LH = (const float*)d_in[1];
    const float* HL = (const float*)d_in[2];
    const float* HH = (const float*)d_in[3];
    float* out = (float*)d_out;

    int total = in_sizes[0] / 4;   // N*C * IPAIRS*WPAIRS = 4096*784 = 3,211,264
    int threads = 256;
    int blocks = (total + threads - 1) / threads;

    idwt_haar_kernel<<<blocks, threads>>>(LL, LH, HL, HH, out, total);
}

// round 5
// speedup vs baseline: 1.0217x; 1.0217x over previous
#include <cuda_runtime.h>

// Inverse 2D Haar DWT, collapsed to the per-2x2-block butterfly:
//   out[2i  ,2j  ] = 0.5*(LL + LH + HL + HH)
//   out[2i  ,2j+1] = 0.5*(LL - LH + HL - HH)
//   out[2i+1,2j  ] = 0.5*(LL + LH - HL - HH)
//   out[2i+1,2j+1] = 0.5*(LL - LH - HL + HH)
//
// Shapes: in (32,128,56,56) f32 x4 -> out (32,128,112,112) f32
//
// Best-measured access shape (R1/R3): one input column-pair per thread,
// float2 loads perfectly linear across the grid (in_off = 2*idx), two
// float4 stores per thread, contiguous across the warp per output row.
// This round: exact grid (no tail predicate) + collapsed index math:
//   idx = ch*(56*28) + i*28 + jj
//   in_off   = 2*idx
//   out_even = ch*12544 + 2*i*112 + 4*jj = 8*idx - 4*(idx % 28)
// so a single %28 replaces the mod/div/mod chain.

#define W_OUT  112
#define WPAIRS 28

__global__ __launch_bounds__(256)
void idwt_haar_kernel(const float* __restrict__ LL,
                      const float* __restrict__ LH,
                      const float* __restrict__ HL,
                      const float* __restrict__ HH,
                      float* __restrict__ out)
{
    unsigned idx = blockIdx.x * blockDim.x + threadIdx.x;   // exact grid, no tail

    unsigned jj      = idx % WPAIRS;
    long     in_off  = 2L * idx;
    long     out_off = 8L * idx - 4L * jj;

    float2 ll = __ldcs(reinterpret_cast<const float2*>(LL + in_off));
    float2 lh = __ldcs(reinterpret_cast<const float2*>(LH + in_off));
    float2 hl = __ldcs(reinterpret_cast<const float2*>(HL + in_off));
    float2 hh = __ldcs(reinterpret_cast<const float2*>(HH + in_off));

    float p0 = ll.x + hl.x, m0 = ll.x - hl.x;
    float q0 = lh.x + hh.x, r0 = lh.x - hh.x;
    float p1 = ll.y + hl.y, m1 = ll.y - hl.y;
    float q1 = lh.y + hh.y, r1 = lh.y - hh.y;

    float4 row_even = make_float4(0.5f * (p0 + q0), 0.5f * (p0 - q0),
                                  0.5f * (p1 + q1), 0.5f * (p1 - q1));
    float4 row_odd  = make_float4(0.5f * (m0 + r0), 0.5f * (m0 - r0),
                                  0.5f * (m1 + r1), 0.5f * (m1 - r1));

    __stcs(reinterpret_cast<float4*>(out + out_off),         row_even);
    __stcs(reinterpret_cast<float4*>(out + out_off + W_OUT), row_odd);
}

extern "C" void kernel_launch(void* const* d_in, const int* in_sizes, int n_in,
                              void* d_out, int out_size)
{
    const float* LL = (const float*)d_in[0];
    const float* LH = (const float*)d_in[1];
    const float* HL = (const float*)d_in[2];
    const float* HH = (const float*)d_in[3];
    float* out = (float*)d_out;

    int total   = in_sizes[0] / 2;          // 6,422,528 = 25088 * 256 exactly
    int threads = 256;
    int blocks  = total / threads;          // exact division, no remainder

    idwt_haar_kernel<<<blocks, threads>>>(LL, LH, HL, HH, out);
}